// round 15
// baseline (speedup 1.0000x reference)
#include <cuda_runtime.h>
#include <cuda_fp16.h>
#include <math.h>
#include <stdint.h>

#define N_NODES 50000
#define N_EDGES 800000
#define F0 128
#define F1 96
#define F2 96
#define F3 40
#define NBLK 74
#define CSR_THREADS 1024
#define CHUNK ((N_NODES + NBLK - 1) / NBLK)   // 676

// ---------------- scratch (static device globals; no allocation) ----------------
__device__ int    g_deg[N_NODES];
__device__ int    g_cur[N_NODES];
__device__ int    g_off[N_NODES + 1];
__device__ int    g_csr[N_EDGES];
__device__ int    g_bsum[NBLK];
__device__ int    g_barrier_ctr;
__device__ int    g_done_ctr;
__device__ __half g_t1[(size_t)N_NODES * F1];
__device__ __half g_h1[(size_t)N_NODES * F1];
__device__ __half g_t2[(size_t)N_NODES * F2];
__device__ __half g_h2[(size_t)N_NODES * F2];
__device__ __half g_t3[(size_t)N_NODES * F3];

// ---------------- PDL intrinsics ----------------
__device__ __forceinline__ void gdc_launch() {
    asm volatile("griddepcontrol.launch_dependents;");
}
__device__ __forceinline__ void gdc_wait() {
    asm volatile("griddepcontrol.wait;" ::: "memory");
}

// ---------------- edge index access ----------------
__device__ __forceinline__ int edge_src(const int* ei, int e, int is64) {
    return is64 ? ei[2 * e] : ei[e];
}
__device__ __forceinline__ int edge_dst(const int* ei, int e, int is64) {
    return is64 ? ei[2 * (N_EDGES + e)] : ei[N_EDGES + e];
}

// ---------------- software grid barrier (74 co-resident blocks) ----------------
__device__ __forceinline__ void grid_barrier(int phase) {
    __syncthreads();
    if (threadIdx.x == 0) {
        __threadfence();
        atomicAdd(&g_barrier_ctr, 1);
        int target = phase * NBLK;
        while ((*(volatile int*)&g_barrier_ctr) - target < 0)
            __nanosleep(64);
    }
    __syncthreads();
    __threadfence();
}

// ---------------- single persistent CSR-build kernel (MLP-4 edge loops) ----------------
__global__ void __launch_bounds__(CSR_THREADS) csr_build_kernel(const int* __restrict__ ei) {
    __shared__ int s_is64;
    __shared__ int s_boff;
    __shared__ int wsum[32];

    int tid  = threadIdx.x;
    int lane = tid & 31, w = tid >> 5;
    int gtid = blockIdx.x * CSR_THREADS + tid;
    constexpr int NT = NBLK * CSR_THREADS;

    if (tid < 32) {
        int acc = 0;
#pragma unroll
        for (int j = 0; j < 4; j++) acc |= ei[1 + 2 * (tid * 4 + j)];
#pragma unroll
        for (int o = 16; o > 0; o >>= 1) acc |= __shfl_xor_sync(0xffffffffu, acc, o);
        if (tid == 0) s_is64 = (acc == 0) ? 1 : 0;
    }
    __syncthreads();
    int is64 = s_is64;

    for (int i = gtid; i < N_NODES; i += NT) g_deg[i] = 0;
    grid_barrier(1);

    {
        int e = gtid;
        for (; e + 3 * NT < N_EDGES; e += 4 * NT) {
            int d0 = edge_dst(ei, e,          is64);
            int d1 = edge_dst(ei, e + NT,     is64);
            int d2 = edge_dst(ei, e + 2 * NT, is64);
            int d3 = edge_dst(ei, e + 3 * NT, is64);
            atomicAdd(&g_deg[d0], 1);
            atomicAdd(&g_deg[d1], 1);
            atomicAdd(&g_deg[d2], 1);
            atomicAdd(&g_deg[d3], 1);
        }
        for (; e < N_EDGES; e += NT)
            atomicAdd(&g_deg[edge_dst(ei, e, is64)], 1);
    }
    grid_barrier(2);

    int cbase = blockIdx.x * CHUNK;
    int i0 = cbase + tid;
    int v = (tid < CHUNK && i0 < N_NODES) ? g_deg[i0] : 0;
    {
        int s = v;
#pragma unroll
        for (int o = 16; o > 0; o >>= 1) s += __shfl_xor_sync(0xffffffffu, s, o);
        if (lane == 0) wsum[w] = s;
        __syncthreads();
        if (w == 0) {
            int t = wsum[lane];
#pragma unroll
            for (int o = 16; o > 0; o >>= 1) t += __shfl_xor_sync(0xffffffffu, t, o);
            if (lane == 0) g_bsum[blockIdx.x] = t;
        }
    }
    grid_barrier(3);

    if (tid == 0) {
        int s = 0;
        for (int b = 0; b < (int)blockIdx.x; b++) s += g_bsum[b];
        s_boff = s;
    }
    __syncthreads();
    {
        int incl = v;
#pragma unroll
        for (int o = 1; o < 32; o <<= 1) {
            int u = __shfl_up_sync(0xffffffffu, incl, o);
            if (lane >= o) incl += u;
        }
        if (lane == 31) wsum[w] = incl;
        __syncthreads();
        if (w == 0) {
            int s = wsum[lane];
#pragma unroll
            for (int o = 1; o < 32; o <<= 1) {
                int u = __shfl_up_sync(0xffffffffu, s, o);
                if (lane >= o) s += u;
            }
            wsum[lane] = s;
        }
        __syncthreads();
        incl += ((w > 0) ? wsum[w - 1] : 0) + s_boff;
        if (tid < CHUNK && i0 < N_NODES) {
            g_off[i0 + 1] = incl;
            g_cur[i0]     = incl - v;
        }
        if (blockIdx.x == 0 && tid == 0) g_off[0] = 0;
    }
    grid_barrier(4);

    {
        int e = gtid;
        for (; e + 3 * NT < N_EDGES; e += 4 * NT) {
            int d0 = edge_dst(ei, e,          is64);
            int d1 = edge_dst(ei, e + NT,     is64);
            int d2 = edge_dst(ei, e + 2 * NT, is64);
            int d3 = edge_dst(ei, e + 3 * NT, is64);
            int s0 = edge_src(ei, e,          is64);
            int s1 = edge_src(ei, e + NT,     is64);
            int s2 = edge_src(ei, e + 2 * NT, is64);
            int s3 = edge_src(ei, e + 3 * NT, is64);
            int p0 = atomicAdd(&g_cur[d0], 1);
            int p1 = atomicAdd(&g_cur[d1], 1);
            int p2 = atomicAdd(&g_cur[d2], 1);
            int p3 = atomicAdd(&g_cur[d3], 1);
            g_csr[p0] = s0;
            g_csr[p1] = s1;
            g_csr[p2] = s2;
            g_csr[p3] = s3;
        }
        for (; e < N_EDGES; e += NT) {
            int d = edge_dst(ei, e, is64);
            int s = edge_src(ei, e, is64);
            int p = atomicAdd(&g_cur[d], 1);
            g_csr[p] = s;
        }
    }

    __syncthreads();
    if (tid == 0) {
        __threadfence();
        int d = atomicAdd(&g_done_ctr, 1);
        if (d == NBLK - 1) {
            g_barrier_ctr = 0;
            g_done_ctr = 0;
            __threadfence();
        }
    }
}

// ---------------- MMA helper ----------------
__device__ __forceinline__ void mma16_f16(float c[4],
                                          uint32_t a0, uint32_t a1, uint32_t a2, uint32_t a3,
                                          uint32_t b0, uint32_t b1) {
    asm volatile(
        "mma.sync.aligned.m16n8k16.row.col.f32.f16.f16.f32 "
        "{%0,%1,%2,%3}, {%4,%5,%6,%7}, {%8,%9}, {%0,%1,%2,%3};"
        : "+f"(c[0]), "+f"(c[1]), "+f"(c[2]), "+f"(c[3])
        : "r"(a0), "r"(a1), "r"(a2), "r"(a3), "r"(b0), "r"(b1));
}

__device__ __forceinline__ void split_h2(float2 f, uint32_t& hi, uint32_t& lo) {
    __half2 h = __floats2half2_rn(f.x, f.y);
    float l0 = f.x - __low2float(h);
    float l1 = f.y - __high2float(h);
    __half2 l = __floats2half2_rn(l0, l1);
    hi = *reinterpret_cast<uint32_t*>(&h);
    lo = *reinterpret_cast<uint32_t*>(&l);
}

// Vectorized B layout: per (kp, grp) a 16-word slot row; word (nt) stored at
// uint4-slot ((nt>>2) ^ (kp&3)), word (nt&3). Reader's kp ≡ tig (mod 4),
// so quarter-warp LDS.128 banks are conflict-free.
// words per copy = KP * 8 * 16.
template <int KP, int N>
__device__ __forceinline__ void stage_w_hiLo(const float* __restrict__ W,
                                             uint32_t* sHi, uint32_t* sLo,
                                             int nthreads) {
    int tid = threadIdx.x;
    for (int i = tid; i < KP * N; i += nthreads) {
        int kp = i / N, n = i % N;
        float2 wp = make_float2(__ldg(W + (2 * kp) * N + n), __ldg(W + (2 * kp + 1) * N + n));
        uint32_t hi, lo;
        split_h2(wp, hi, lo);
        int nt = n >> 3, grp = n & 7;
        int idx = (kp * 32 + grp * 4 + ((nt >> 2) ^ (kp & 3))) * 4 + (nt & 3);
        sHi[idx] = hi;
        sLo[idx] = lo;
    }
}

// B-fragment MMA body over all nt tiles for one k-step (both hi and lo passes),
// for accumulator pair (cA, cB) with A fragments (aA*, aB*).
template <int N>
__device__ __forceinline__ void mma_ktile(
        const uint32_t* sHi, const uint32_t* sLo,
        int kp0, int kp1, int grp, int tig,
        const uint32_t aA[4], const uint32_t aAlo[4], bool useAlo,
        const uint32_t aB[4], const uint32_t aBlo[4],
        float cA[][4], float cB[][4]) {
    constexpr int NT = N / 8;
    constexpr int QMAX = (NT + 3) / 4;
    int base0 = (kp0 * 8 + grp) * 4;   // uint4 units
    int base1 = (kp1 * 8 + grp) * 4;
#pragma unroll
    for (int q = 0; q < QMAX; q++) {
        int s0 = base0 + (q ^ tig);
        int s1 = base1 + (q ^ tig);
        uint4 h0 = ((const uint4*)sHi)[s0];
        uint4 h1 = ((const uint4*)sHi)[s1];
        uint4 l0 = ((const uint4*)sLo)[s0];
        uint4 l1 = ((const uint4*)sLo)[s1];
        const uint32_t* h0w = (const uint32_t*)&h0;
        const uint32_t* h1w = (const uint32_t*)&h1;
        const uint32_t* l0w = (const uint32_t*)&l0;
        const uint32_t* l1w = (const uint32_t*)&l1;
#pragma unroll
        for (int j = 0; j < 4; j++) {
            int nt = q * 4 + j;
            if (nt >= NT) break;
            mma16_f16(cA[nt], aA[0], aA[1], aA[2], aA[3], h0w[j], h1w[j]);
            if (useAlo)
                mma16_f16(cA[nt], aAlo[0], aAlo[1], aAlo[2], aAlo[3], h0w[j], h1w[j]);
            mma16_f16(cA[nt], aA[0], aA[1], aA[2], aA[3], l0w[j], l1w[j]);
            mma16_f16(cB[nt], aB[0], aB[1], aB[2], aB[3], h0w[j], h1w[j]);
            if (useAlo)
                mma16_f16(cB[nt], aBlo[0], aBlo[1], aBlo[2], aBlo[3], h0w[j], h1w[j]);
            mma16_f16(cB[nt], aB[0], aB[1], aB[2], aB[3], l0w[j], l1w[j]);
        }
    }
}

// ---------------- GEMM1: fp16 MMA, A=x (fp32->hi/lo), B=W1 (hi/lo), 3 passes ----------------
template <int K, int N>
__global__ void __launch_bounds__(192, 2) mma_gemm_h1_kernel(
        const float* __restrict__ X, const float* __restrict__ W,
        __half* __restrict__ Y) {
    constexpr int NT = N / 8;
    constexpr int KP = K / 2;
    extern __shared__ uint32_t smem[];
    uint32_t* sHi = smem;
    uint32_t* sLo = smem + KP * 8 * 16;

    gdc_launch();
    stage_w_hiLo<KP, N>(W, sHi, sLo, 192);
    __syncthreads();

    int tid = threadIdx.x;
    int warp = tid >> 5, lane = tid & 31;
    int tig = lane & 3, grp = lane >> 2;
    int row0 = blockIdx.x * 192 + warp * 32;
    int r0 = row0 + grp,      r1 = row0 + grp + 8;
    int r2 = row0 + grp + 16, r3 = row0 + grp + 24;
    const float* xr0 = X + (size_t)((r0 < N_NODES) ? r0 : (N_NODES - 1)) * K;
    const float* xr1 = X + (size_t)((r1 < N_NODES) ? r1 : (N_NODES - 1)) * K;
    const float* xr2 = X + (size_t)((r2 < N_NODES) ? r2 : (N_NODES - 1)) * K;
    const float* xr3 = X + (size_t)((r3 < N_NODES) ? r3 : (N_NODES - 1)) * K;

    float c0[NT][4], c1[NT][4];
#pragma unroll
    for (int nt = 0; nt < NT; nt++)
#pragma unroll
        for (int j = 0; j < 4; j++) { c0[nt][j] = 0.f; c1[nt][j] = 0.f; }

#pragma unroll 1
    for (int k0 = 0; k0 < K; k0 += 16) {
        float2 f00 = *(const float2*)(xr0 + k0 + 2 * tig);
        float2 f01 = *(const float2*)(xr1 + k0 + 2 * tig);
        float2 f02 = *(const float2*)(xr0 + k0 + 2 * tig + 8);
        float2 f03 = *(const float2*)(xr1 + k0 + 2 * tig + 8);
        float2 f10 = *(const float2*)(xr2 + k0 + 2 * tig);
        float2 f11 = *(const float2*)(xr3 + k0 + 2 * tig);
        float2 f12 = *(const float2*)(xr2 + k0 + 2 * tig + 8);
        float2 f13 = *(const float2*)(xr3 + k0 + 2 * tig + 8);
        uint32_t ah0[4], al0[4], ah1[4], al1[4];
        split_h2(f00, ah0[0], al0[0]); split_h2(f01, ah0[1], al0[1]);
        split_h2(f02, ah0[2], al0[2]); split_h2(f03, ah0[3], al0[3]);
        split_h2(f10, ah1[0], al1[0]); split_h2(f11, ah1[1], al1[1]);
        split_h2(f12, ah1[2], al1[2]); split_h2(f13, ah1[3], al1[3]);

        int kp0 = (k0 >> 1) + tig;
        int kp1 = kp0 + 4;
        mma_ktile<N>(sHi, sLo, kp0, kp1, grp, tig,
                     ah0, al0, true, ah1, al1, c0, c1);
    }

#pragma unroll
    for (int nt = 0; nt < NT; nt++) {
        int col = nt * 8 + 2 * tig;
        if (r0 < N_NODES)
            *(__half2*)(Y + (size_t)r0 * N + col) = __floats2half2_rn(c0[nt][0], c0[nt][1]);
        if (r1 < N_NODES)
            *(__half2*)(Y + (size_t)r1 * N + col) = __floats2half2_rn(c0[nt][2], c0[nt][3]);
        if (r2 < N_NODES)
            *(__half2*)(Y + (size_t)r2 * N + col) = __floats2half2_rn(c1[nt][0], c1[nt][1]);
        if (r3 < N_NODES)
            *(__half2*)(Y + (size_t)r3 * N + col) = __floats2half2_rn(c1[nt][2], c1[nt][3]);
    }
}

// ---------------- GEMM2/3: fp16 m16n8k16, A fp16 direct, W = hi+lo (2 passes), PDL ----------------
template <int K, int N>
__global__ void __launch_bounds__(192, 2) mma_gemm_h_kernel(
        const __half* __restrict__ X, const float* __restrict__ W,
        __half* __restrict__ Y) {
    constexpr int NT = N / 8;
    constexpr int KP = K / 2;
    extern __shared__ uint32_t smem[];
    uint32_t* sHi = smem;
    uint32_t* sLo = smem + KP * 8 * 16;

    gdc_launch();
    stage_w_hiLo<KP, N>(W, sHi, sLo, 192);
    __syncthreads();

    int tid = threadIdx.x;
    int warp = tid >> 5, lane = tid & 31;
    int tig = lane & 3, grp = lane >> 2;
    int row0 = blockIdx.x * 192 + warp * 32;
    int r0 = row0 + grp,      r1 = row0 + grp + 8;
    int r2 = row0 + grp + 16, r3 = row0 + grp + 24;
    const __half* xr0 = X + (size_t)((r0 < N_NODES) ? r0 : (N_NODES - 1)) * K;
    const __half* xr1 = X + (size_t)((r1 < N_NODES) ? r1 : (N_NODES - 1)) * K;
    const __half* xr2 = X + (size_t)((r2 < N_NODES) ? r2 : (N_NODES - 1)) * K;
    const __half* xr3 = X + (size_t)((r3 < N_NODES) ? r3 : (N_NODES - 1)) * K;

    float c0[NT][4], c1[NT][4];
#pragma unroll
    for (int nt = 0; nt < NT; nt++)
#pragma unroll
        for (int j = 0; j < 4; j++) { c0[nt][j] = 0.f; c1[nt][j] = 0.f; }

    gdc_wait();   // predecessor (agg) output X valid from here

#pragma unroll 1
    for (int k0 = 0; k0 < K; k0 += 16) {
        uint32_t a0[4], a1[4];
        a0[0] = __ldg((const uint32_t*)(xr0 + k0 + 2 * tig));
        a0[1] = __ldg((const uint32_t*)(xr1 + k0 + 2 * tig));
        a0[2] = __ldg((const uint32_t*)(xr0 + k0 + 2 * tig + 8));
        a0[3] = __ldg((const uint32_t*)(xr1 + k0 + 2 * tig + 8));
        a1[0] = __ldg((const uint32_t*)(xr2 + k0 + 2 * tig));
        a1[1] = __ldg((const uint32_t*)(xr3 + k0 + 2 * tig));
        a1[2] = __ldg((const uint32_t*)(xr2 + k0 + 2 * tig + 8));
        a1[3] = __ldg((const uint32_t*)(xr3 + k0 + 2 * tig + 8));

        int kp0 = (k0 >> 1) + tig;
        int kp1 = kp0 + 4;
        mma_ktile<N>(sHi, sLo, kp0, kp1, grp, tig,
                     a0, a0, false, a1, a1, c0, c1);
    }

#pragma unroll
    for (int nt = 0; nt < NT; nt++) {
        int col = nt * 8 + 2 * tig;
        if (r0 < N_NODES)
            *(__half2*)(Y + (size_t)r0 * N + col) = __floats2half2_rn(c0[nt][0], c0[nt][1]);
        if (r1 < N_NODES)
            *(__half2*)(Y + (size_t)r1 * N + col) = __floats2half2_rn(c0[nt][2], c0[nt][3]);
        if (r2 < N_NODES)
            *(__half2*)(Y + (size_t)r2 * N + col) = __floats2half2_rn(c1[nt][0], c1[nt][1]);
        if (r3 < N_NODES)
            *(__half2*)(Y + (size_t)r3 * N + col) = __floats2half2_rn(c1[nt][2], c1[nt][3]);
    }
}

// ---------------- gather aggregation (fp16 in, fp32 accum) + fused epilogue, PDL ----------------
__device__ __forceinline__ void acc_h4(float4& acc, uint2 v) {
    float2 f0 = __half22float2(*reinterpret_cast<__half2*>(&v.x));
    float2 f1 = __half22float2(*reinterpret_cast<__half2*>(&v.y));
    acc.x += f0.x; acc.y += f0.y; acc.z += f1.x; acc.w += f1.y;
}

// EPI 0: relu(acc+bias) -> fp16   EPI 1: log_softmax(acc+bias) -> fp32
template <int D, int EPI>
__global__ void agg_kernel(const __half* __restrict__ xin, const float* __restrict__ bias,
                           void* __restrict__ xout) {
    gdc_launch();
    int gw   = (blockIdx.x * blockDim.x + threadIdx.x) >> 5;
    int lane = threadIdx.x & 31;
    if (gw >= N_NODES) { gdc_wait(); return; }
    constexpr int D4 = D / 4;
    float4 acc = make_float4(0.f, 0.f, 0.f, 0.f);
    int beg = g_off[gw], end = g_off[gw + 1];
    float4 bb = (lane < D4) ? ((const float4*)bias)[lane] : make_float4(0.f, 0.f, 0.f, 0.f);

    gdc_wait();

    int e = beg;
    for (; e + 3 < end; e += 4) {
        int s0 = g_csr[e], s1 = g_csr[e + 1], s2 = g_csr[e + 2], s3 = g_csr[e + 3];
        if (lane < D4) {
            uint2 v0 = __ldg((const uint2*)(xin + (size_t)s0 * D) + lane);
            uint2 v1 = __ldg((const uint2*)(xin + (size_t)s1 * D) + lane);
            uint2 v2 = __ldg((const uint2*)(xin + (size_t)s2 * D) + lane);
            uint2 v3 = __ldg((const uint2*)(xin + (size_t)s3 * D) + lane);
            acc_h4(acc, v0);
            acc_h4(acc, v1);
            acc_h4(acc, v2);
            acc_h4(acc, v3);
        }
    }
    for (; e < end; e++) {
        int s0 = g_csr[e];
        if (lane < D4) {
            uint2 v = __ldg((const uint2*)(xin + (size_t)s0 * D) + lane);
            acc_h4(acc, v);
        }
    }
    acc.x += bb.x; acc.y += bb.y; acc.z += bb.z; acc.w += bb.w;

    if (EPI == 0) {
        if (lane < D4) {
            __half2 o0 = __floats2half2_rn(fmaxf(acc.x, 0.f), fmaxf(acc.y, 0.f));
            __half2 o1 = __floats2half2_rn(fmaxf(acc.z, 0.f), fmaxf(acc.w, 0.f));
            uint2 pack;
            pack.x = *reinterpret_cast<uint32_t*>(&o0);
            pack.y = *reinterpret_cast<uint32_t*>(&o1);
            ((uint2*)((__half*)xout + (size_t)gw * D))[lane] = pack;
        }
    } else {
        float m = (lane < D4)
                ? fmaxf(fmaxf(acc.x, acc.y), fmaxf(acc.z, acc.w))
                : -INFINITY;
#pragma unroll
        for (int o = 16; o > 0; o >>= 1) m = fmaxf(m, __shfl_xor_sync(0xffffffffu, m, o));
        float s = (lane < D4)
                ? (expf(acc.x - m) + expf(acc.y - m)) + (expf(acc.z - m) + expf(acc.w - m))
                : 0.f;
#pragma unroll
        for (int o = 16; o > 0; o >>= 1) s += __shfl_xor_sync(0xffffffffu, s, o);
        float l = m + logf(s);
        if (lane < D4) {
            acc.x -= l; acc.y -= l; acc.z -= l; acc.w -= l;
            ((float4*)((float*)xout + (size_t)gw * D))[lane] = acc;
        }
    }
}

// ---------------- launch ----------------
extern "C" void kernel_launch(void* const* d_in, const int* in_sizes, int n_in,
                              void* d_out, int out_size) {
    const float* x  = (const float*)d_in[0];
    const float* W1 = (const float*)d_in[1];
    const float* b1 = (const float*)d_in[2];
    const float* W2 = (const float*)d_in[3];
    const float* b2 = (const float*)d_in[4];
    const float* W3 = (const float*)d_in[5];
    const float* b3 = (const float*)d_in[6];
    const int*   ei = (const int*)d_in[7];
    float* out = (float*)d_out;

    __half *p_t1, *p_h1, *p_t2, *p_h2, *p_t3;
    cudaGetSymbolAddress((void**)&p_t1, g_t1);
    cudaGetSymbolAddress((void**)&p_h1, g_h1);
    cudaGetSymbolAddress((void**)&p_t2, g_t2);
    cudaGetSymbolAddress((void**)&p_h2, g_h2);
    cudaGetSymbolAddress((void**)&p_t3, g_t3);

    // smem = 2 copies (hi/lo) * KP * 8 rows * 16 words * 4 B
    const int smem1 = 2 * (F0 / 2) * 8 * 16 * 4;   // 64 KB
    const int smem2 = 2 * (F1 / 2) * 8 * 16 * 4;   // 48 KB
    const int smem3 = 2 * (F2 / 2) * 8 * 16 * 4;   // 48 KB

    static cudaStream_t sB = nullptr;
    static cudaEvent_t ev_fork = nullptr, ev_join = nullptr;
    if (!sB) {
        cudaStreamCreateWithFlags(&sB, cudaStreamNonBlocking);
        cudaEventCreateWithFlags(&ev_fork, cudaEventDisableTiming);
        cudaEventCreateWithFlags(&ev_join, cudaEventDisableTiming);
        cudaFuncSetAttribute(mma_gemm_h1_kernel<F0, F1>,
                             cudaFuncAttributeMaxDynamicSharedMemorySize, smem1);
        cudaFuncSetAttribute(mma_gemm_h_kernel<F1, F2>,
                             cudaFuncAttributeMaxDynamicSharedMemorySize, smem2);
        cudaFuncSetAttribute(mma_gemm_h_kernel<F2, F3>,
                             cudaFuncAttributeMaxDynamicSharedMemorySize, smem3);
    }

    // fork: persistent CSR build on sB, GEMM1 on main stream
    cudaEventRecord(ev_fork, 0);
    cudaStreamWaitEvent(sB, ev_fork, 0);
    csr_build_kernel<<<NBLK, CSR_THREADS, 0, sB>>>(ei);
    cudaEventRecord(ev_join, sB);

    const int agg_grid  = (N_NODES * 32 + 255) / 256;
    const int gemm_grid = (N_NODES + 191) / 192;

    // main stream: t1 = x @ W1
    mma_gemm_h1_kernel<F0, F1><<<gemm_grid, 192, smem1>>>(x, W1, p_t1);

    // join: aggregation needs CSR
    cudaStreamWaitEvent(0, ev_join, 0);

    cudaLaunchAttribute pdl[1];
    pdl[0].id = cudaLaunchAttributeProgrammaticStreamSerialization;
    pdl[0].val.programmaticStreamSerializationAllowed = 1;

    auto launch_agg = [&](auto kern, int grid, const __half* xin, const float* b, void* xo) {
        cudaLaunchConfig_t cfg = {};
        cfg.gridDim = dim3(grid);
        cfg.blockDim = dim3(256);
        cfg.dynamicSmemBytes = 0;
        cfg.stream = 0;
        cfg.attrs = pdl;
        cfg.numAttrs = 1;
        cudaLaunchKernelEx(&cfg, kern, xin, b, xo);
    };
    auto launch_gemm = [&](auto kern, int smem, const __half* X, const float* W, __half* Y) {
        cudaLaunchConfig_t cfg = {};
        cfg.gridDim = dim3(gemm_grid);
        cfg.blockDim = dim3(192);
        cfg.dynamicSmemBytes = (size_t)smem;
        cfg.stream = 0;
        cfg.attrs = pdl;
        cfg.numAttrs = 1;
        cudaLaunchKernelEx(&cfg, kern, X, W, Y);
    };

    // layer 1: h1 = relu(agg(t1) + b1)
    launch_agg(agg_kernel<F1, 0>, agg_grid, p_t1, b1, (void*)p_h1);
    // layer 2
    launch_gemm(mma_gemm_h_kernel<F1, F2>, smem2, p_h1, W2, p_t2);
    launch_agg(agg_kernel<F2, 0>, agg_grid, p_t2, b2, (void*)p_h2);
    // layer 3 + log_softmax
    launch_gemm(mma_gemm_h_kernel<F2, F3>, smem3, p_h2, W3, p_t3);
    launch_agg(agg_kernel<F3, 1>, agg_grid, p_t3, b3, (void*)out);
}

// round 16
// speedup vs baseline: 1.0327x; 1.0327x over previous
#include <cuda_runtime.h>
#include <cuda_fp16.h>
#include <math.h>
#include <stdint.h>

#define N_NODES 50000
#define N_EDGES 800000
#define F0 128
#define F1 96
#define F2 96
#define F3 40
#define NBLK 74
#define CSR_THREADS 1024
#define CHUNK ((N_NODES + NBLK - 1) / NBLK)   // 676

// ---------------- scratch (static device globals; no allocation) ----------------
__device__ int    g_deg[N_NODES];
__device__ int    g_cur[N_NODES];
__device__ int    g_off[N_NODES + 1];
__device__ int    g_csr[N_EDGES];
__device__ int    g_bsum[NBLK];
__device__ int    g_barrier_ctr;
__device__ int    g_done_ctr;
__device__ __half g_t1[(size_t)N_NODES * F1];
__device__ __half g_h1[(size_t)N_NODES * F1];
__device__ __half g_t2[(size_t)N_NODES * F2];
__device__ __half g_h2[(size_t)N_NODES * F2];
__device__ __half g_t3[(size_t)N_NODES * F3];

// ---------------- PDL intrinsics ----------------
__device__ __forceinline__ void gdc_launch() {
    asm volatile("griddepcontrol.launch_dependents;");
}
__device__ __forceinline__ void gdc_wait() {
    asm volatile("griddepcontrol.wait;" ::: "memory");
}

// ---------------- edge index access ----------------
__device__ __forceinline__ int edge_src(const int* ei, int e, int is64) {
    return is64 ? ei[2 * e] : ei[e];
}
__device__ __forceinline__ int edge_dst(const int* ei, int e, int is64) {
    return is64 ? ei[2 * (N_EDGES + e)] : ei[N_EDGES + e];
}

// ---------------- software grid barrier (74 co-resident blocks) ----------------
__device__ __forceinline__ void grid_barrier(int phase) {
    __syncthreads();
    if (threadIdx.x == 0) {
        __threadfence();
        atomicAdd(&g_barrier_ctr, 1);
        int target = phase * NBLK;
        while ((*(volatile int*)&g_barrier_ctr) - target < 0)
            __nanosleep(64);
    }
    __syncthreads();
    __threadfence();
}

// ---------------- single persistent CSR-build kernel (MLP-4 edge loops) ----------------
__global__ void __launch_bounds__(CSR_THREADS) csr_build_kernel(const int* __restrict__ ei) {
    __shared__ int s_is64;
    __shared__ int s_boff;
    __shared__ int wsum[32];

    int tid  = threadIdx.x;
    int lane = tid & 31, w = tid >> 5;
    int gtid = blockIdx.x * CSR_THREADS + tid;
    constexpr int NT = NBLK * CSR_THREADS;

    if (tid < 32) {
        int acc = 0;
#pragma unroll
        for (int j = 0; j < 4; j++) acc |= ei[1 + 2 * (tid * 4 + j)];
#pragma unroll
        for (int o = 16; o > 0; o >>= 1) acc |= __shfl_xor_sync(0xffffffffu, acc, o);
        if (tid == 0) s_is64 = (acc == 0) ? 1 : 0;
    }
    __syncthreads();
    int is64 = s_is64;

    for (int i = gtid; i < N_NODES; i += NT) g_deg[i] = 0;
    grid_barrier(1);

    {
        int e = gtid;
        for (; e + 3 * NT < N_EDGES; e += 4 * NT) {
            int d0 = edge_dst(ei, e,          is64);
            int d1 = edge_dst(ei, e + NT,     is64);
            int d2 = edge_dst(ei, e + 2 * NT, is64);
            int d3 = edge_dst(ei, e + 3 * NT, is64);
            atomicAdd(&g_deg[d0], 1);
            atomicAdd(&g_deg[d1], 1);
            atomicAdd(&g_deg[d2], 1);
            atomicAdd(&g_deg[d3], 1);
        }
        for (; e < N_EDGES; e += NT)
            atomicAdd(&g_deg[edge_dst(ei, e, is64)], 1);
    }
    grid_barrier(2);

    int cbase = blockIdx.x * CHUNK;
    int i0 = cbase + tid;
    int v = (tid < CHUNK && i0 < N_NODES) ? g_deg[i0] : 0;
    {
        int s = v;
#pragma unroll
        for (int o = 16; o > 0; o >>= 1) s += __shfl_xor_sync(0xffffffffu, s, o);
        if (lane == 0) wsum[w] = s;
        __syncthreads();
        if (w == 0) {
            int t = wsum[lane];
#pragma unroll
            for (int o = 16; o > 0; o >>= 1) t += __shfl_xor_sync(0xffffffffu, t, o);
            if (lane == 0) g_bsum[blockIdx.x] = t;
        }
    }
    grid_barrier(3);

    if (tid == 0) {
        int s = 0;
        for (int b = 0; b < (int)blockIdx.x; b++) s += g_bsum[b];
        s_boff = s;
    }
    __syncthreads();
    {
        int incl = v;
#pragma unroll
        for (int o = 1; o < 32; o <<= 1) {
            int u = __shfl_up_sync(0xffffffffu, incl, o);
            if (lane >= o) incl += u;
        }
        if (lane == 31) wsum[w] = incl;
        __syncthreads();
        if (w == 0) {
            int s = wsum[lane];
#pragma unroll
            for (int o = 1; o < 32; o <<= 1) {
                int u = __shfl_up_sync(0xffffffffu, s, o);
                if (lane >= o) s += u;
            }
            wsum[lane] = s;
        }
        __syncthreads();
        incl += ((w > 0) ? wsum[w - 1] : 0) + s_boff;
        if (tid < CHUNK && i0 < N_NODES) {
            g_off[i0 + 1] = incl;
            g_cur[i0]     = incl - v;
        }
        if (blockIdx.x == 0 && tid == 0) g_off[0] = 0;
    }
    grid_barrier(4);

    {
        int e = gtid;
        for (; e + 3 * NT < N_EDGES; e += 4 * NT) {
            int d0 = edge_dst(ei, e,          is64);
            int d1 = edge_dst(ei, e + NT,     is64);
            int d2 = edge_dst(ei, e + 2 * NT, is64);
            int d3 = edge_dst(ei, e + 3 * NT, is64);
            int s0 = edge_src(ei, e,          is64);
            int s1 = edge_src(ei, e + NT,     is64);
            int s2 = edge_src(ei, e + 2 * NT, is64);
            int s3 = edge_src(ei, e + 3 * NT, is64);
            int p0 = atomicAdd(&g_cur[d0], 1);
            int p1 = atomicAdd(&g_cur[d1], 1);
            int p2 = atomicAdd(&g_cur[d2], 1);
            int p3 = atomicAdd(&g_cur[d3], 1);
            g_csr[p0] = s0;
            g_csr[p1] = s1;
            g_csr[p2] = s2;
            g_csr[p3] = s3;
        }
        for (; e < N_EDGES; e += NT) {
            int d = edge_dst(ei, e, is64);
            int s = edge_src(ei, e, is64);
            int p = atomicAdd(&g_cur[d], 1);
            g_csr[p] = s;
        }
    }

    __syncthreads();
    if (tid == 0) {
        __threadfence();
        int d = atomicAdd(&g_done_ctr, 1);
        if (d == NBLK - 1) {
            g_barrier_ctr = 0;
            g_done_ctr = 0;
            __threadfence();
        }
    }
}

// ---------------- MMA helper ----------------
__device__ __forceinline__ void mma16_f16(float c[4],
                                          uint32_t a0, uint32_t a1, uint32_t a2, uint32_t a3,
                                          uint32_t b0, uint32_t b1) {
    asm volatile(
        "mma.sync.aligned.m16n8k16.row.col.f32.f16.f16.f32 "
        "{%0,%1,%2,%3}, {%4,%5,%6,%7}, {%8,%9}, {%0,%1,%2,%3};"
        : "+f"(c[0]), "+f"(c[1]), "+f"(c[2]), "+f"(c[3])
        : "r"(a0), "r"(a1), "r"(a2), "r"(a3), "r"(b0), "r"(b1));
}

__device__ __forceinline__ void split_h2(float2 f, uint32_t& hi, uint32_t& lo) {
    __half2 h = __floats2half2_rn(f.x, f.y);
    float l0 = f.x - __low2float(h);
    float l1 = f.y - __high2float(h);
    __half2 l = __floats2half2_rn(l0, l1);
    hi = *reinterpret_cast<uint32_t*>(&h);
    lo = *reinterpret_cast<uint32_t*>(&l);
}

// PS padding: PS % 16 == 4 -> uint2 row stride (2*PS words) % 32 == 8
// -> LDS.64 phases hit 16 distinct banks (t*8 + g*2 all distinct mod 32).
#define PS_OF(N) ((N) + ((4 - ((N) % 16) + 16) % 16))

// stage W as packed uint2{hi,lo} at sW[kp*PS + n]
template <int KP, int N, int PS>
__device__ __forceinline__ void stage_w_packed(const float* __restrict__ W,
                                               uint2* sW, int nthreads) {
    int tid = threadIdx.x;
    for (int i = tid; i < KP * N; i += nthreads) {
        int kp = i / N, n = i % N;
        float2 wp = make_float2(__ldg(W + (2 * kp) * N + n), __ldg(W + (2 * kp + 1) * N + n));
        uint2 p;
        split_h2(wp, p.x, p.y);
        sW[kp * PS + n] = p;
    }
}

// ---------------- GEMM1: fp16 MMA, A=x (fp32->hi/lo), B=W1 packed, 3 passes ----------------
template <int K, int N>
__global__ void __launch_bounds__(192, 2) mma_gemm_h1_kernel(
        const float* __restrict__ X, const float* __restrict__ W,
        __half* __restrict__ Y) {
    constexpr int NT = N / 8;
    constexpr int KP = K / 2;
    constexpr int PS = PS_OF(N);
    extern __shared__ uint2 smem_u2[];
    uint2* sW = smem_u2;

    gdc_launch();
    stage_w_packed<KP, N, PS>(W, sW, 192);
    __syncthreads();

    int tid = threadIdx.x;
    int warp = tid >> 5, lane = tid & 31;
    int tig = lane & 3, grp = lane >> 2;
    int row0 = blockIdx.x * 192 + warp * 32;
    int r0 = row0 + grp,      r1 = row0 + grp + 8;
    int r2 = row0 + grp + 16, r3 = row0 + grp + 24;
    const float* xr0 = X + (size_t)((r0 < N_NODES) ? r0 : (N_NODES - 1)) * K;
    const float* xr1 = X + (size_t)((r1 < N_NODES) ? r1 : (N_NODES - 1)) * K;
    const float* xr2 = X + (size_t)((r2 < N_NODES) ? r2 : (N_NODES - 1)) * K;
    const float* xr3 = X + (size_t)((r3 < N_NODES) ? r3 : (N_NODES - 1)) * K;

    float c0[NT][4], c1[NT][4];
#pragma unroll
    for (int nt = 0; nt < NT; nt++)
#pragma unroll
        for (int j = 0; j < 4; j++) { c0[nt][j] = 0.f; c1[nt][j] = 0.f; }

    // A prefetch double-buffer (fp32)
    float2 fa[8];
    auto loadA = [&](float2 fb[8], int k0) {
        fb[0] = *(const float2*)(xr0 + k0 + 2 * tig);
        fb[1] = *(const float2*)(xr1 + k0 + 2 * tig);
        fb[2] = *(const float2*)(xr0 + k0 + 2 * tig + 8);
        fb[3] = *(const float2*)(xr1 + k0 + 2 * tig + 8);
        fb[4] = *(const float2*)(xr2 + k0 + 2 * tig);
        fb[5] = *(const float2*)(xr3 + k0 + 2 * tig);
        fb[6] = *(const float2*)(xr2 + k0 + 2 * tig + 8);
        fb[7] = *(const float2*)(xr3 + k0 + 2 * tig + 8);
    };
    loadA(fa, 0);

#pragma unroll 1
    for (int k0 = 0; k0 < K; k0 += 16) {
        float2 fn[8];
        if (k0 + 16 < K) loadA(fn, k0 + 16);

        uint32_t ah0[4], al0[4], ah1[4], al1[4];
        split_h2(fa[0], ah0[0], al0[0]); split_h2(fa[1], ah0[1], al0[1]);
        split_h2(fa[2], ah0[2], al0[2]); split_h2(fa[3], ah0[3], al0[3]);
        split_h2(fa[4], ah1[0], al1[0]); split_h2(fa[5], ah1[1], al1[1]);
        split_h2(fa[6], ah1[2], al1[2]); split_h2(fa[7], ah1[3], al1[3]);

        int kp0 = (k0 >> 1) + tig;
        int kp1 = kp0 + 4;
        const uint2* rB0 = sW + kp0 * PS + grp;
        const uint2* rB1 = sW + kp1 * PS + grp;
#pragma unroll
        for (int nt = 0; nt < NT; nt++) {
            uint2 b0 = rB0[nt * 8];
            uint2 b1 = rB1[nt * 8];
            mma16_f16(c0[nt], ah0[0], ah0[1], ah0[2], ah0[3], b0.x, b1.x);  // hi*hi
            mma16_f16(c0[nt], al0[0], al0[1], al0[2], al0[3], b0.x, b1.x);  // lo*hi
            mma16_f16(c0[nt], ah0[0], ah0[1], ah0[2], ah0[3], b0.y, b1.y);  // hi*lo
            mma16_f16(c1[nt], ah1[0], ah1[1], ah1[2], ah1[3], b0.x, b1.x);
            mma16_f16(c1[nt], al1[0], al1[1], al1[2], al1[3], b0.x, b1.x);
            mma16_f16(c1[nt], ah1[0], ah1[1], ah1[2], ah1[3], b0.y, b1.y);
        }
#pragma unroll
        for (int j = 0; j < 8; j++) fa[j] = fn[j];
    }

#pragma unroll
    for (int nt = 0; nt < NT; nt++) {
        int col = nt * 8 + 2 * tig;
        if (r0 < N_NODES)
            *(__half2*)(Y + (size_t)r0 * N + col) = __floats2half2_rn(c0[nt][0], c0[nt][1]);
        if (r1 < N_NODES)
            *(__half2*)(Y + (size_t)r1 * N + col) = __floats2half2_rn(c0[nt][2], c0[nt][3]);
        if (r2 < N_NODES)
            *(__half2*)(Y + (size_t)r2 * N + col) = __floats2half2_rn(c1[nt][0], c1[nt][1]);
        if (r3 < N_NODES)
            *(__half2*)(Y + (size_t)r3 * N + col) = __floats2half2_rn(c1[nt][2], c1[nt][3]);
    }
}

// ---------------- GEMM2/3: fp16 m16n8k16, A fp16 direct, W packed hi/lo, PDL ----------------
template <int K, int N>
__global__ void __launch_bounds__(192, 2) mma_gemm_h_kernel(
        const __half* __restrict__ X, const float* __restrict__ W,
        __half* __restrict__ Y) {
    constexpr int NT = N / 8;
    constexpr int KP = K / 2;
    constexpr int PS = PS_OF(N);
    extern __shared__ uint2 smem_u2[];
    uint2* sW = smem_u2;

    gdc_launch();
    stage_w_packed<KP, N, PS>(W, sW, 192);
    __syncthreads();

    int tid = threadIdx.x;
    int warp = tid >> 5, lane = tid & 31;
    int tig = lane & 3, grp = lane >> 2;
    int row0 = blockIdx.x * 192 + warp * 32;
    int r0 = row0 + grp,      r1 = row0 + grp + 8;
    int r2 = row0 + grp + 16, r3 = row0 + grp + 24;
    const __half* xr0 = X + (size_t)((r0 < N_NODES) ? r0 : (N_NODES - 1)) * K;
    const __half* xr1 = X + (size_t)((r1 < N_NODES) ? r1 : (N_NODES - 1)) * K;
    const __half* xr2 = X + (size_t)((r2 < N_NODES) ? r2 : (N_NODES - 1)) * K;
    const __half* xr3 = X + (size_t)((r3 < N_NODES) ? r3 : (N_NODES - 1)) * K;

    float c0[NT][4], c1[NT][4];
#pragma unroll
    for (int nt = 0; nt < NT; nt++)
#pragma unroll
        for (int j = 0; j < 4; j++) { c0[nt][j] = 0.f; c1[nt][j] = 0.f; }

    gdc_wait();   // predecessor (agg) output X valid from here

    uint32_t aC[8];
    auto loadA = [&](uint32_t ab[8], int k0) {
        ab[0] = __ldg((const uint32_t*)(xr0 + k0 + 2 * tig));
        ab[1] = __ldg((const uint32_t*)(xr1 + k0 + 2 * tig));
        ab[2] = __ldg((const uint32_t*)(xr0 + k0 + 2 * tig + 8));
        ab[3] = __ldg((const uint32_t*)(xr1 + k0 + 2 * tig + 8));
        ab[4] = __ldg((const uint32_t*)(xr2 + k0 + 2 * tig));
        ab[5] = __ldg((const uint32_t*)(xr3 + k0 + 2 * tig));
        ab[6] = __ldg((const uint32_t*)(xr2 + k0 + 2 * tig + 8));
        ab[7] = __ldg((const uint32_t*)(xr3 + k0 + 2 * tig + 8));
    };
    loadA(aC, 0);

#pragma unroll 1
    for (int k0 = 0; k0 < K; k0 += 16) {
        uint32_t aN[8];
        if (k0 + 16 < K) loadA(aN, k0 + 16);

        int kp0 = (k0 >> 1) + tig;
        int kp1 = kp0 + 4;
        const uint2* rB0 = sW + kp0 * PS + grp;
        const uint2* rB1 = sW + kp1 * PS + grp;
#pragma unroll
        for (int nt = 0; nt < NT; nt++) {
            uint2 b0 = rB0[nt * 8];
            uint2 b1 = rB1[nt * 8];
            mma16_f16(c0[nt], aC[0], aC[1], aC[2], aC[3], b0.x, b1.x);
            mma16_f16(c0[nt], aC[0], aC[1], aC[2], aC[3], b0.y, b1.y);
            mma16_f16(c1[nt], aC[4], aC[5], aC[6], aC[7], b0.x, b1.x);
            mma16_f16(c1[nt], aC[4], aC[5], aC[6], aC[7], b0.y, b1.y);
        }
#pragma unroll
        for (int j = 0; j < 8; j++) aC[j] = aN[j];
    }

#pragma unroll
    for (int nt = 0; nt < NT; nt++) {
        int col = nt * 8 + 2 * tig;
        if (r0 < N_NODES)
            *(__half2*)(Y + (size_t)r0 * N + col) = __floats2half2_rn(c0[nt][0], c0[nt][1]);
        if (r1 < N_NODES)
            *(__half2*)(Y + (size_t)r1 * N + col) = __floats2half2_rn(c0[nt][2], c0[nt][3]);
        if (r2 < N_NODES)
            *(__half2*)(Y + (size_t)r2 * N + col) = __floats2half2_rn(c1[nt][0], c1[nt][1]);
        if (r3 < N_NODES)
            *(__half2*)(Y + (size_t)r3 * N + col) = __floats2half2_rn(c1[nt][2], c1[nt][3]);
    }
}

// ---------------- gather aggregation (fp16 in, fp32 accum) + fused epilogue, PDL ----------------
__device__ __forceinline__ void acc_h4(float4& acc, uint2 v) {
    float2 f0 = __half22float2(*reinterpret_cast<__half2*>(&v.x));
    float2 f1 = __half22float2(*reinterpret_cast<__half2*>(&v.y));
    acc.x += f0.x; acc.y += f0.y; acc.z += f1.x; acc.w += f1.y;
}

// EPI 0: relu(acc+bias) -> fp16   EPI 1: log_softmax(acc+bias) -> fp32
template <int D, int EPI>
__global__ void agg_kernel(const __half* __restrict__ xin, const float* __restrict__ bias,
                           void* __restrict__ xout) {
    gdc_launch();
    int gw   = (blockIdx.x * blockDim.x + threadIdx.x) >> 5;
    int lane = threadIdx.x & 31;
    if (gw >= N_NODES) { gdc_wait(); return; }
    constexpr int D4 = D / 4;
    float4 acc = make_float4(0.f, 0.f, 0.f, 0.f);
    int beg = g_off[gw], end = g_off[gw + 1];
    float4 bb = (lane < D4) ? ((const float4*)bias)[lane] : make_float4(0.f, 0.f, 0.f, 0.f);

    gdc_wait();

    int e = beg;
    for (; e + 3 < end; e += 4) {
        int s0 = g_csr[e], s1 = g_csr[e + 1], s2 = g_csr[e + 2], s3 = g_csr[e + 3];
        if (lane < D4) {
            uint2 v0 = __ldg((const uint2*)(xin + (size_t)s0 * D) + lane);
            uint2 v1 = __ldg((const uint2*)(xin + (size_t)s1 * D) + lane);
            uint2 v2 = __ldg((const uint2*)(xin + (size_t)s2 * D) + lane);
            uint2 v3 = __ldg((const uint2*)(xin + (size_t)s3 * D) + lane);
            acc_h4(acc, v0);
            acc_h4(acc, v1);
            acc_h4(acc, v2);
            acc_h4(acc, v3);
        }
    }
    for (; e < end; e++) {
        int s0 = g_csr[e];
        if (lane < D4) {
            uint2 v = __ldg((const uint2*)(xin + (size_t)s0 * D) + lane);
            acc_h4(acc, v);
        }
    }
    acc.x += bb.x; acc.y += bb.y; acc.z += bb.z; acc.w += bb.w;

    if (EPI == 0) {
        if (lane < D4) {
            __half2 o0 = __floats2half2_rn(fmaxf(acc.x, 0.f), fmaxf(acc.y, 0.f));
            __half2 o1 = __floats2half2_rn(fmaxf(acc.z, 0.f), fmaxf(acc.w, 0.f));
            uint2 pack;
            pack.x = *reinterpret_cast<uint32_t*>(&o0);
            pack.y = *reinterpret_cast<uint32_t*>(&o1);
            ((uint2*)((__half*)xout + (size_t)gw * D))[lane] = pack;
        }
    } else {
        float m = (lane < D4)
                ? fmaxf(fmaxf(acc.x, acc.y), fmaxf(acc.z, acc.w))
                : -INFINITY;
#pragma unroll
        for (int o = 16; o > 0; o >>= 1) m = fmaxf(m, __shfl_xor_sync(0xffffffffu, m, o));
        float s = (lane < D4)
                ? (expf(acc.x - m) + expf(acc.y - m)) + (expf(acc.z - m) + expf(acc.w - m))
                : 0.f;
#pragma unroll
        for (int o = 16; o > 0; o >>= 1) s += __shfl_xor_sync(0xffffffffu, s, o);
        float l = m + logf(s);
        if (lane < D4) {
            acc.x -= l; acc.y -= l; acc.z -= l; acc.w -= l;
            ((float4*)((float*)xout + (size_t)gw * D))[lane] = acc;
        }
    }
}

// ---------------- launch ----------------
extern "C" void kernel_launch(void* const* d_in, const int* in_sizes, int n_in,
                              void* d_out, int out_size) {
    const float* x  = (const float*)d_in[0];
    const float* W1 = (const float*)d_in[1];
    const float* b1 = (const float*)d_in[2];
    const float* W2 = (const float*)d_in[3];
    const float* b2 = (const float*)d_in[4];
    const float* W3 = (const float*)d_in[5];
    const float* b3 = (const float*)d_in[6];
    const int*   ei = (const int*)d_in[7];
    float* out = (float*)d_out;

    __half *p_t1, *p_h1, *p_t2, *p_h2, *p_t3;
    cudaGetSymbolAddress((void**)&p_t1, g_t1);
    cudaGetSymbolAddress((void**)&p_h1, g_h1);
    cudaGetSymbolAddress((void**)&p_t2, g_t2);
    cudaGetSymbolAddress((void**)&p_h2, g_h2);
    cudaGetSymbolAddress((void**)&p_t3, g_t3);

    // smem = KP * PS * 8 bytes (packed uint2 hi/lo)
    const int smem1 = (F0 / 2) * PS_OF(F1) * 8;   // 64*100*8 = 51.2 KB
    const int smem2 = (F1 / 2) * PS_OF(F2) * 8;   // 48*100*8 = 38.4 KB
    const int smem3 = (F2 / 2) * PS_OF(F3) * 8;   // 48*52*8  = 20.0 KB

    static cudaStream_t sB = nullptr;
    static cudaEvent_t ev_fork = nullptr, ev_join = nullptr;
    if (!sB) {
        cudaStreamCreateWithFlags(&sB, cudaStreamNonBlocking);
        cudaEventCreateWithFlags(&ev_fork, cudaEventDisableTiming);
        cudaEventCreateWithFlags(&ev_join, cudaEventDisableTiming);
        cudaFuncSetAttribute(mma_gemm_h1_kernel<F0, F1>,
                             cudaFuncAttributeMaxDynamicSharedMemorySize, smem1);
        cudaFuncSetAttribute(mma_gemm_h_kernel<F1, F2>,
                             cudaFuncAttributeMaxDynamicSharedMemorySize, smem2);
        cudaFuncSetAttribute(mma_gemm_h_kernel<F2, F3>,
                             cudaFuncAttributeMaxDynamicSharedMemorySize, smem3);
    }

    // fork: persistent CSR build on sB, GEMM1 on main stream
    cudaEventRecord(ev_fork, 0);
    cudaStreamWaitEvent(sB, ev_fork, 0);
    csr_build_kernel<<<NBLK, CSR_THREADS, 0, sB>>>(ei);
    cudaEventRecord(ev_join, sB);

    const int agg_grid  = (N_NODES * 32 + 255) / 256;
    const int gemm_grid = (N_NODES + 191) / 192;

    // main stream: t1 = x @ W1
    mma_gemm_h1_kernel<F0, F1><<<gemm_grid, 192, smem1>>>(x, W1, p_t1);

    // join: aggregation needs CSR
    cudaStreamWaitEvent(0, ev_join, 0);

    cudaLaunchAttribute pdl[1];
    pdl[0].id = cudaLaunchAttributeProgrammaticStreamSerialization;
    pdl[0].val.programmaticStreamSerializationAllowed = 1;

    auto launch_agg = [&](auto kern, int grid, const __half* xin, const float* b, void* xo) {
        cudaLaunchConfig_t cfg = {};
        cfg.gridDim = dim3(grid);
        cfg.blockDim = dim3(256);
        cfg.dynamicSmemBytes = 0;
        cfg.stream = 0;
        cfg.attrs = pdl;
        cfg.numAttrs = 1;
        cudaLaunchKernelEx(&cfg, kern, xin, b, xo);
    };
    auto launch_gemm = [&](auto kern, int smem, const __half* X, const float* W, __half* Y) {
        cudaLaunchConfig_t cfg = {};
        cfg.gridDim = dim3(gemm_grid);
        cfg.blockDim = dim3(192);
        cfg.dynamicSmemBytes = (size_t)smem;
        cfg.stream = 0;
        cfg.attrs = pdl;
        cfg.numAttrs = 1;
        cudaLaunchKernelEx(&cfg, kern, X, W, Y);
    };

    // layer 1: h1 = relu(agg(t1) + b1)
    launch_agg(agg_kernel<F1, 0>, agg_grid, p_t1, b1, (void*)p_h1);
    // layer 2
    launch_gemm(mma_gemm_h_kernel<F1, F2>, smem2, p_h1, W2, p_t2);
    launch_agg(agg_kernel<F2, 0>, agg_grid, p_t2, b2, (void*)p_h2);
    // layer 3 + log_softmax
    launch_gemm(mma_gemm_h_kernel<F2, F3>, smem3, p_h2, W3, p_t3);
    launch_agg(agg_kernel<F3, 1>, agg_grid, p_t3, b3, (void*)out);
}